// round 7
// baseline (speedup 1.0000x reference)
#include <cuda_runtime.h>
#include <cstdint>

// LambdaLoss: B=4096 lists, L=128 items.
// loss = mean over valid lists of
//        [ sum_{i,j: rel_i>rel_j} (rel_i-rel_j)*softplus(-(p_i-p_j)) / cnt ]
//
// Factorized: softplus(-(p_w-p_l)) = ln(1 + e^{p_l}*e^{-p_w}); precompute
// e_i = exp(p_i), rec_i = exp(-p_i) -> one lg2 per pair, no per-pair exp.
// Counting-sort by rel: winner = higher sorted index, so |rd| is always the
// correct weight and one index-derived select picks the orientation.
// R7: one list per 128-thread block (2x warp supply vs R5) — thread j owns
// sorted item j, ring k=1..63 covers every unordered pair at ring distance
// 1..63 exactly once; distance-64 handled by threads j<64 (warp-uniform).
// 128*63 + 64 = 8128 = C(128,2).

#define LL_B   4096
#define LL_L   128
#define LOG2E  1.4426950408889634f
#define LN2    0.6931471805599453f

__device__ float g_sum   = 0.0f;
__device__ int   g_valid = 0;
__device__ int   g_done  = 0;

__device__ __forceinline__ float fast_ex2(float x) {
    float r; asm("ex2.approx.f32 %0, %1;" : "=f"(r) : "f"(x)); return r;
}
__device__ __forceinline__ float fast_lg2(float x) {
    float r; asm("lg2.approx.f32 %0, %1;" : "=f"(r) : "f"(x)); return r;
}

__global__ __launch_bounds__(128) void ll_main_kernel(
    const float* __restrict__ pred,
    const float* __restrict__ rel,
    float* __restrict__ out)
{
    __shared__ float4 S[192];        // sorted (e, rec, rel, _); [128,192) dup
    __shared__ int    hist[8];
    __shared__ int    base[8];
    __shared__ float  wsum[4];

    const int j    = threadIdx.x;
    const int list = blockIdx.x;

    const float p = pred[list * LL_L + j];
    const float r = rel [list * LL_L + j];
    const int   c = (int)r;          // rel in {0..4}

    // exp work independent of the sort — overlap with barriers
    const float q  = p * LOG2E;
    const float e  = fast_ex2(q);
    const float rc = fast_ex2(-q);

    if (j < 8) hist[j] = 0;
    __syncthreads();
    atomicAdd(&hist[c], 1);
    __syncthreads();
    if (j == 0) {
        int a = 0;
#pragma unroll
        for (int cc = 0; cc < 5; cc++) { base[cc] = a; a += hist[cc]; }
    }
    __syncthreads();

    // rank + scatter; writers to [0,64) also write the ring-wrap duplicate
    const int pos = atomicAdd(&base[c], 1);
    const float4 tu = make_float4(e, rc, r, 0.0f);
    S[pos] = tu;
    if (pos < 64) S[pos + 128] = tu;
    __syncthreads();

    // thread j owns SORTED item j
    const float4 self = S[j];
    const float eS = self.x, rcS = self.y, rS = self.z;

    float acc0 = 0.0f, acc1 = 0.0f, acc2 = 0.0f, acc3 = 0.0f;

    // pair body: partner = sorted index j+k (dup region handles wrap).
    // no wrap  -> partner wins: t = e_self * rec_p,  rd = r_p - r_self >= 0
    // wrap     -> self wins:    t = e_p * rec_self,  rd = r_self - r_p >= 0
    // |rd| covers both; select is index-derived (no data dependence).
#define LL_PAIR(K, ACC)                                                  \
    {                                                                    \
        const float4 v = S[j + (K)];                                     \
        const bool  nw = (j + (K)) < LL_L;                               \
        float rd = v.z - rS;                                             \
        float tt = nw ? (eS * v.y) : (v.x * rcS);                        \
        ACC = fmaf(fabsf(rd), fast_lg2(1.0f + tt), ACC);                 \
    }

#pragma unroll
    for (int k = 1; k <= 60; k += 4) {
        LL_PAIR(k,     acc0)
        LL_PAIR(k + 1, acc1)
        LL_PAIR(k + 2, acc2)
        LL_PAIR(k + 3, acc3)
    }
    LL_PAIR(61, acc0)
    LL_PAIR(62, acc1)
    LL_PAIR(63, acc2)

    // distance-64 pairs: threads j<64 (warps 0,1 — uniform), never wraps
    if (j < LL_L / 2) {
        const float4 v = S[j + 64];
        acc3 = fmaf(v.z - rS, fast_lg2(1.0f + eS * v.y), acc3);
    }
#undef LL_PAIR

    float acc = (acc0 + acc1) + (acc2 + acc3);

    // block reduction (4 warps)
#pragma unroll
    for (int off = 16; off; off >>= 1)
        acc += __shfl_xor_sync(0xffffffffu, acc, off);
    if ((j & 31) == 0) wsum[j >> 5] = acc;
    __syncthreads();

    if (j == 0) {
        float s = (wsum[0] + wsum[1] + wsum[2] + wsum[3]) * LN2;
        const int n0 = hist[0], n1 = hist[1], n2 = hist[2];
        const int n3 = hist[3], n4 = hist[4];
        const int cnt = n1 * n0
                      + n2 * (n0 + n1)
                      + n3 * (n0 + n1 + n2)
                      + n4 * (n0 + n1 + n2 + n3);
        if (cnt > 0) {
            atomicAdd(&g_sum, s / (float)cnt);
            atomicAdd(&g_valid, 1);
        }
        __threadfence();
        const int prev = atomicAdd(&g_done, 1);
        if (prev == gridDim.x - 1) {
            const float gs = g_sum;
            const int   gv = g_valid;
            out[0] = (gv > 0) ? (gs / (float)gv) : 0.0f;
            g_sum   = 0.0f;
            g_valid = 0;
            g_done  = 0;
        }
    }
}

extern "C" void kernel_launch(void* const* d_in, const int* in_sizes, int n_in,
                              void* d_out, int out_size)
{
    const float* pred = (const float*)d_in[0];
    const float* rel  = (const float*)d_in[1];
    float* out = (float*)d_out;

    ll_main_kernel<<<LL_B, LL_L>>>(pred, rel, out);
}